// round 1
// baseline (speedup 1.0000x reference)
#include <cuda_runtime.h>
#include <math.h>

// RepulsionLoss: points [4, 8192, 3] f32 -> scalar f32
// loss = ALPHA * mean_{b,i,k} (RADIUS - dn) * exp(-dn^2 / H^2)
// where dn = sqrt(max(d2_k, 1e-12)) over the K=8 smallest pairwise squared
// distances (including self, d2=0) within each batch.
//
// Key: we never need neighbor indices or coordinates — only the K smallest d2
// per query. Fused brute-force KNN with register-resident sorted top-8.

#define BATCH   4
#define NPTS    8192
#define KNN     8
#define RADIUS  0.07f
#define H2_INV  (1.0f / (0.03f * 0.03f))
#define ALPHA   0.1f

#define TILE    2048      // candidates per smem tile (32 KB as float4)
#define BLOCK   128       // threads per block, 1 query per thread

__device__ float g_acc;

__global__ void zero_acc_kernel() {
    g_acc = 0.0f;
}

__global__ __launch_bounds__(BLOCK) void repulsion_knn_kernel(const float* __restrict__ pts) {
    __shared__ float4 s_tile[TILE];
    __shared__ float s_warp[BLOCK / 32];

    const int blocks_per_batch = NPTS / BLOCK;           // 64
    const int b  = blockIdx.x / blocks_per_batch;
    const int qi = (blockIdx.x % blocks_per_batch) * BLOCK + threadIdx.x;

    const float* __restrict__ base = pts + (size_t)b * NPTS * 3;

    const float qx = base[qi * 3 + 0];
    const float qy = base[qi * 3 + 1];
    const float qz = base[qi * 3 + 2];

    // sorted ascending; best[KNN-1] is the current worst-of-best (threshold)
    float best[KNN];
#pragma unroll
    for (int k = 0; k < KNN; ++k) best[k] = 3.0e38f;

    for (int t0 = 0; t0 < NPTS; t0 += TILE) {
        // cooperative tile load: pack xyz into float4 for single LDS.128 reads
        for (int c = threadIdx.x; c < TILE; c += BLOCK) {
            const int j = t0 + c;
            s_tile[c] = make_float4(base[j * 3 + 0], base[j * 3 + 1], base[j * 3 + 2], 0.0f);
        }
        __syncthreads();

#pragma unroll 4
        for (int c = 0; c < TILE; ++c) {
            const float4 p = s_tile[c];              // broadcast LDS.128
            const float dx = qx - p.x;
            const float dy = qy - p.y;
            const float dz = qz - p.z;
            const float d2 = fmaf(dx, dx, fmaf(dy, dy, dz * dz));
            if (d2 < best[KNN - 1]) {
                // insert: place at end, single bubble pass restores sorted order
                best[KNN - 1] = d2;
#pragma unroll
                for (int k = KNN - 1; k > 0; --k) {
                    const float lo = fminf(best[k - 1], best[k]);
                    const float hi = fmaxf(best[k - 1], best[k]);
                    best[k - 1] = lo;
                    best[k]     = hi;
                }
            }
        }
        __syncthreads();
    }

    // per-thread contribution over its 8 nearest (self included: d2 = 0)
    float s = 0.0f;
#pragma unroll
    for (int k = 0; k < KNN; ++k) {
        const float d2 = best[k];
        const float dn = sqrtf(fmaxf(d2, 1e-12f));
        const float w  = __expf(-d2 * H2_INV);
        s = fmaf(RADIUS - dn, w, s);
    }

    // warp reduce
#pragma unroll
    for (int off = 16; off > 0; off >>= 1)
        s += __shfl_xor_sync(0xffffffffu, s, off);

    if ((threadIdx.x & 31) == 0) s_warp[threadIdx.x >> 5] = s;
    __syncthreads();

    if (threadIdx.x == 0) {
        float bs = 0.0f;
#pragma unroll
        for (int w = 0; w < BLOCK / 32; ++w) bs += s_warp[w];
        atomicAdd(&g_acc, bs);
    }
}

__global__ void finalize_kernel(float* __restrict__ out) {
    out[0] = ALPHA * g_acc * (1.0f / (float)(BATCH * NPTS * KNN));
}

extern "C" void kernel_launch(void* const* d_in, const int* in_sizes, int n_in,
                              void* d_out, int out_size) {
    const float* pts = (const float*)d_in[0];
    float* out = (float*)d_out;

    zero_acc_kernel<<<1, 1>>>();
    const int grid = BATCH * (NPTS / BLOCK);   // 256 blocks
    repulsion_knn_kernel<<<grid, BLOCK>>>(pts);
    finalize_kernel<<<1, 1>>>(out);
}

// round 2
// speedup vs baseline: 1.3918x; 1.3918x over previous
#include <cuda_runtime.h>
#include <math.h>

// RepulsionLoss: points [4, 8192, 3] f32 -> scalar f32
// Fused brute-force KNN (K=8) + loss reduction.
//
// R2: slice-per-warp decomposition. Block = 256 threads = 8 warps.
//   - lane l of every warp owns query (block_query_base + l)  -> 32 queries/block
//   - warp w scans candidate slice [w*1024, (w+1)*1024)       -> slices partition N
//   - per-lane register-resident sorted top-8 per slice
//   - smem merge of the 8 slice-top8s -> exact global top-8 -> loss terms
// 262144 threads total (~40 warps/SM) vs 32768 in R1 (~8 warps/SM).

#define BATCH   4
#define NPTS    8192
#define KNN     8
#define RADIUS  0.07f
#define H2_INV  (1.0f / (0.03f * 0.03f))
#define ALPHA   0.1f

#define NSLICE   8                 // warps per block = candidate slices
#define SLICE_N  (NPTS / NSLICE)   // 1024 candidates per slice
#define TILE     256               // candidates per per-warp smem tile
#define BLOCK    (32 * NSLICE)     // 256 threads
#define QPB      32                // queries per block (one per lane)

__device__ float g_acc;

__global__ void zero_acc_kernel() { g_acc = 0.0f; }

__global__ __launch_bounds__(BLOCK) void repulsion_knn_kernel(const float* __restrict__ pts) {
    __shared__ float4 s_tile[NSLICE][TILE];    // 32 KB
    __shared__ float  s_merge[QPB][NSLICE * KNN + 1];  // stride 65 -> conflict-free

    const int w = threadIdx.x >> 5;   // slice / warp id
    const int l = threadIdx.x & 31;   // lane = local query id

    const int blocks_per_batch = NPTS / QPB;          // 256
    const int b  = blockIdx.x / blocks_per_batch;
    const int qg = blockIdx.x % blocks_per_batch;
    const int q  = qg * QPB + l;

    const float* __restrict__ base = pts + (size_t)b * NPTS * 3;

    const float qx = base[q * 3 + 0];
    const float qy = base[q * 3 + 1];
    const float qz = base[q * 3 + 2];

    // sorted ascending; best[KNN-1] = current worst-of-best (threshold)
    float best[KNN];
#pragma unroll
    for (int k = 0; k < KNN; ++k) best[k] = 3.0e38f;

    const int c0 = w * SLICE_N;

    for (int t0 = 0; t0 < SLICE_N; t0 += TILE) {
        // per-warp cooperative tile load (xyz packed to float4 for LDS.128)
#pragma unroll
        for (int r = 0; r < TILE / 32; ++r) {
            const int c = r * 32 + l;
            const int j = c0 + t0 + c;
            s_tile[w][c] = make_float4(base[j * 3 + 0], base[j * 3 + 1],
                                       base[j * 3 + 2], 0.0f);
        }
        __syncwarp();

#pragma unroll 4
        for (int c = 0; c < TILE; ++c) {
            const float4 p = s_tile[w][c];   // warp-uniform broadcast LDS.128
            const float dx = qx - p.x;
            const float dy = qy - p.y;
            const float dz = qz - p.z;
            const float d2 = fmaf(dx, dx, fmaf(dy, dy, dz * dz));
            if (d2 < best[KNN - 1]) {
                best[KNN - 1] = d2;
#pragma unroll
                for (int k = KNN - 1; k > 0; --k) {
                    const float lo = fminf(best[k - 1], best[k]);
                    const float hi = fmaxf(best[k - 1], best[k]);
                    best[k - 1] = lo;
                    best[k]     = hi;
                }
            }
        }
        __syncwarp();
    }

    // publish this slice's top-8 for merging
#pragma unroll
    for (int k = 0; k < KNN; ++k) s_merge[l][w * KNN + k] = best[k];
    __syncthreads();

    // warp 0 merges: lane l takes query l, selects top-8 of the 64 slice values
    if (w == 0) {
        float m[KNN];
#pragma unroll
        for (int k = 0; k < KNN; ++k) m[k] = 3.0e38f;

#pragma unroll 4
        for (int i = 0; i < NSLICE * KNN; ++i) {
            const float d2 = s_merge[l][i];
            if (d2 < m[KNN - 1]) {
                m[KNN - 1] = d2;
#pragma unroll
                for (int k = KNN - 1; k > 0; --k) {
                    const float lo = fminf(m[k - 1], m[k]);
                    const float hi = fmaxf(m[k - 1], m[k]);
                    m[k - 1] = lo;
                    m[k]     = hi;
                }
            }
        }

        float s = 0.0f;
#pragma unroll
        for (int k = 0; k < KNN; ++k) {
            const float d2 = m[k];
            const float dn = sqrtf(fmaxf(d2, 1e-12f));
            const float wgt = __expf(-d2 * H2_INV);
            s = fmaf(RADIUS - dn, wgt, s);
        }

#pragma unroll
        for (int off = 16; off > 0; off >>= 1)
            s += __shfl_xor_sync(0xffffffffu, s, off);

        if (l == 0) atomicAdd(&g_acc, s);
    }
}

__global__ void finalize_kernel(float* __restrict__ out) {
    out[0] = ALPHA * g_acc * (1.0f / (float)(BATCH * NPTS * KNN));
}

extern "C" void kernel_launch(void* const* d_in, const int* in_sizes, int n_in,
                              void* d_out, int out_size) {
    const float* pts = (const float*)d_in[0];
    float* out = (float*)d_out;

    zero_acc_kernel<<<1, 1>>>();
    const int grid = BATCH * (NPTS / QPB);   // 1024 blocks
    repulsion_knn_kernel<<<grid, BLOCK>>>(pts);
    finalize_kernel<<<1, 1>>>(out);
}